// round 5
// baseline (speedup 1.0000x reference)
#include <cuda_runtime.h>
#include <cuda_bf16.h>
#include <math_constants.h>

#define THREADS 256
#define D 4096
#define V4T (D / 4 / THREADS)   // 4 float4 per thread
#define NW (THREADS / 32)       // 8 warps
#define CANDCAP 64
#define SORTN 32

__device__ __forceinline__ void cp_async16(unsigned saddr, const void* gaddr) {
    asm volatile("cp.async.cg.shared.global [%0], [%1], 16;" :: "r"(saddr), "l"(gaddr) : "memory");
}

__global__ __launch_bounds__(THREADS, 8)
void sparsemax_kernel(const float* __restrict__ in, float* __restrict__ out)
{
    __shared__ float sz[D];                 // 16KB row staging
    __shared__ float red[NW];
    __shared__ float redb[NW];
    __shared__ float cand[CANDCAP];
    __shared__ int   s_cnt;
    __shared__ float s_tau;
    __shared__ int   s_done;

    const long long row = blockIdx.x;
    const float* __restrict__ rin = in  + row * (long long)D;
    float*       __restrict__ rout = out + row * (long long)D;

    const int t    = threadIdx.x;
    const int lane = t & 31;
    const int wid  = t >> 5;
    const unsigned FULL = 0xFFFFFFFFu;

    // ---- Stage row into smem via cp.async (no registers, L1 bypass)
    const unsigned sbase = (unsigned)__cvta_generic_to_shared(sz);
#pragma unroll
    for (int i = 0; i < V4T; ++i) {
        int v4 = t + i * THREADS;
        cp_async16(sbase + v4 * 16u, rin + v4 * 4);
    }
    asm volatile("cp.async.wait_all;" ::: "memory");
    __syncwarp();

    if (t == 0) s_cnt = 0;

    // ---- Quad maxes + warp max over own slice (own cp.asyncs complete)
    const float4* sv = reinterpret_cast<const float4*>(sz);
    float qm[V4T];
    float m;
#pragma unroll
    for (int i = 0; i < V4T; ++i) {
        float4 v = sv[t + i * THREADS];
        qm[i] = fmaxf(fmaxf(v.x, v.y), fmaxf(v.z, v.w));
    }
    m = fmaxf(fmaxf(qm[0], qm[1]), fmaxf(qm[2], qm[3]));
#pragma unroll
    for (int off = 16; off >= 1; off >>= 1)
        m = fmaxf(m, __shfl_xor_sync(FULL, m, off));
    if (lane == 0) red[wid] = m;
    __syncthreads();                        // B0

    float zmax = red[0];
#pragma unroll
    for (int w = 1; w < NW; ++w) zmax = fmaxf(zmax, red[w]);
    const float lo = zmax - 1.0f;           // tau in [lo, zmax)

    // ---- Compaction: quad-skip via registers, re-probe smem only on warp hit
#pragma unroll
    for (int q = 0; q < V4T; ++q) {
        if (__any_sync(FULL, qm[q] > lo)) {
            if (qm[q] > lo) {
                float4 v = sv[t + q * THREADS];
                if (v.x > lo) { int p = atomicAdd(&s_cnt, 1); if (p < CANDCAP) cand[p] = v.x; }
                if (v.y > lo) { int p = atomicAdd(&s_cnt, 1); if (p < CANDCAP) cand[p] = v.y; }
                if (v.z > lo) { int p = atomicAdd(&s_cnt, 1); if (p < CANDCAP) cand[p] = v.z; }
                if (v.w > lo) { int p = atomicAdd(&s_cnt, 1); if (p < CANDCAP) cand[p] = v.w; }
            }
        }
    }
    __syncthreads();                        // B1
    const int cnt = s_cnt;

    float tau;
    if (cnt <= SORTN) {
        // ---- Exact closed-form solve, redundantly in every warp (no more barriers)
        float v = (lane < cnt) ? cand[lane] : -CUDART_INF_F;

        // 32-lane bitonic sort, descending
#pragma unroll
        for (int k = 2; k <= 32; k <<= 1) {
#pragma unroll
            for (int j = k >> 1; j > 0; j >>= 1) {
                float w = __shfl_xor_sync(FULL, v, j);
                bool lower   = ((lane & j) == 0);
                bool descBlk = ((lane & k) == 0);
                v = (lower == descBlk) ? fmaxf(v, w) : fminf(v, w);
            }
        }
        // inclusive prefix sum
        float csum = v;
#pragma unroll
        for (int off = 1; off < 32; off <<= 1) {
            float u = __shfl_up_sync(FULL, csum, off);
            if (lane >= off) csum += u;
        }
        // support size: largest j with 1 + (j+1)*v_j > csum_j
        float r = (float)(lane + 1);
        bool cond = (lane < cnt) && (1.0f + r * v > csum);
        unsigned msk = __ballot_sync(FULL, cond);
        int kidx = 31 - __clz(msk);
        float csk = __shfl_sync(FULL, csum, kidx);
        tau = (csk - 1.0f) / (float)(kidx + 1);
    } else {
        // ---- Fallback: block-wide Newton over smem (arbitrary data correctness)
        if (t == 0) s_tau = lo;
        __syncthreads();
        float tloc = s_tau;
        for (int it = 0; it < 48; ++it) {
            float s = 0.0f, k = 0.0f;
#pragma unroll
            for (int i = 0; i < V4T; ++i) {
                float4 v = sv[t + i * THREADS];
                float d;
                d = v.x - tloc; if (d > 0.0f) { s += d; k += 1.0f; }
                d = v.y - tloc; if (d > 0.0f) { s += d; k += 1.0f; }
                d = v.z - tloc; if (d > 0.0f) { s += d; k += 1.0f; }
                d = v.w - tloc; if (d > 0.0f) { s += d; k += 1.0f; }
            }
#pragma unroll
            for (int off = 16; off >= 1; off >>= 1) {
                s += __shfl_xor_sync(FULL, s, off);
                k += __shfl_xor_sync(FULL, k, off);
            }
            if (lane == 0) { red[wid] = s; redb[wid] = k; }
            __syncthreads();
            if (t == 0) {
                float S = 0.0f, K = 0.0f;
#pragma unroll
                for (int w = 0; w < NW; ++w) { S += red[w]; K += redb[w]; }
                float delta = (S - 1.0f) / K;
                s_tau  = tloc + delta;
                s_done = (delta < 1e-7f);
            }
            __syncthreads();
            tloc = s_tau;
            if (s_done) break;
        }
        tau = s_tau;
    }

    // ---- Epilogue: out = max(z - tau, 0), streaming stores
#pragma unroll
    for (int i = 0; i < V4T; ++i) {
        int v4 = t + i * THREADS;
        float4 v = sv[v4];
        float4 o;
        o.x = fmaxf(v.x - tau, 0.0f);
        o.y = fmaxf(v.y - tau, 0.0f);
        o.z = fmaxf(v.z - tau, 0.0f);
        o.w = fmaxf(v.w - tau, 0.0f);
        __stcs(reinterpret_cast<float4*>(rout) + v4, o);
    }
}

extern "C" void kernel_launch(void* const* d_in, const int* in_sizes, int n_in,
                              void* d_out, int out_size)
{
    const float* in  = (const float*)d_in[0];
    float*       out = (float*)d_out;
    const int n_rows = in_sizes[0] / D;   // 16384
    sparsemax_kernel<<<n_rows, THREADS>>>(in, out);
}